// round 1
// baseline (speedup 1.0000x reference)
#include <cuda_runtime.h>
#include <cuda_bf16.h>

// Problem constants
#define BB 256      // batch
#define TT 128      // time
#define DD 256      // input dim
#define HH 512      // layer1 hidden
#define H2 1024     // 2H
#define H4 2048     // 4H
#define H8 4096     // 8H

// -------- Device scratch (no allocations allowed) --------
// Layer-1 gate pre-activations, fwd slab then bwd slab: [2][T][B][4H]
__device__ float g_X1[2u * TT * BB * H4];           // 512 MiB
// concat(f_seq, b_seq): [T][B][2H]
__device__ float g_comb[(size_t)TT * BB * H2];      // 128 MiB
// Layer-2 gate pre-activations: [T][B][8H]
__device__ float g_Gs[(size_t)TT * BB * H8];        // 512 MiB
// Packed recurrent weights for layer1: [2][4H][H]
__device__ float g_Whh1[2u * H4 * HH];
// States
__device__ float g_h1[2 * BB * HH];
__device__ float g_c1[2 * BB * HH];
__device__ float g_hs[BB * H2];
__device__ float g_cs[BB * H2];

__device__ __forceinline__ float sigf(float x) { return 1.f / (1.f + expf(-x)); }

// -------- zero init of recurrent state (graph is replayed -> must reset) ----
__global__ void zero_state() {
    int i = blockIdx.x * blockDim.x + threadIdx.x;   // 262144 threads
    if (i < 2 * BB * HH) { g_h1[i] = 0.f; g_c1[i] = 0.f; }
    if (i < BB * H2)     { g_hs[i] = 0.f; g_cs[i] = 0.f; }
}

// -------- Generic 64x64x16 fp32 GEMM: C = A @ W^T (+bias) (+C) --------------
// A: [M,K] row stride lda (element stride), W: [N,K] row stride ldw.
// blockIdx.z shifts A/W/C by sAz/sWz/sCz (for time/direction batching).
// M,N assumed multiples of 64; K multiple of 16. No bounds checks.
template <bool ADD_C, bool HAS_BIAS>
__global__ void __launch_bounds__(256) gemm64(
    const float* __restrict__ A, int lda, long long sAz,
    const float* __restrict__ W, int ldw, long long sWz,
    const float* __restrict__ bias,
    float* __restrict__ C, int ldc, long long sCz,
    int K)
{
    __shared__ __align__(16) float As[16][68];
    __shared__ __align__(16) float Bs[16][68];

    A += (long long)blockIdx.z * sAz;
    W += (long long)blockIdx.z * sWz;
    C += (long long)blockIdx.z * sCz;

    const int tid = threadIdx.x;
    const int tx  = tid & 15;
    const int ty  = tid >> 4;
    const long long m0 = (long long)blockIdx.y * 64;
    const long long n0 = (long long)blockIdx.x * 64;

    const int lrow = tid >> 2;         // 0..63
    const int lk   = (tid & 3) << 2;   // 0,4,8,12

    const float* Ap = A + (m0 + lrow) * (long long)lda + lk;
    const float* Wp = W + (n0 + lrow) * (long long)ldw + lk;

    float acc[4][4];
#pragma unroll
    for (int i = 0; i < 4; ++i)
#pragma unroll
        for (int j = 0; j < 4; ++j) acc[i][j] = 0.f;

    for (int k0 = 0; k0 < K; k0 += 16) {
        float4 av = *(const float4*)(Ap + k0);
        float4 wv = *(const float4*)(Wp + k0);
        __syncthreads();
        As[lk + 0][lrow] = av.x; As[lk + 1][lrow] = av.y;
        As[lk + 2][lrow] = av.z; As[lk + 3][lrow] = av.w;
        Bs[lk + 0][lrow] = wv.x; Bs[lk + 1][lrow] = wv.y;
        Bs[lk + 2][lrow] = wv.z; Bs[lk + 3][lrow] = wv.w;
        __syncthreads();
#pragma unroll
        for (int k = 0; k < 16; ++k) {
            float a[4], b[4];
            *(float4*)a = *(const float4*)&As[k][ty << 2];
            *(float4*)b = *(const float4*)&Bs[k][tx << 2];
#pragma unroll
            for (int i = 0; i < 4; ++i)
#pragma unroll
                for (int j = 0; j < 4; ++j) acc[i][j] += a[i] * b[j];
        }
    }

    float bcol[4];
    if (HAS_BIAS) {
        *(float4*)bcol = *(const float4*)&bias[n0 + (tx << 2)];
    }
#pragma unroll
    for (int i = 0; i < 4; ++i) {
        float* Crow = C + (m0 + (ty << 2) + i) * (long long)ldc + n0 + (tx << 2);
        float4 prev = make_float4(0.f, 0.f, 0.f, 0.f);
        if (ADD_C) prev = *(const float4*)Crow;
        float4 v;
        v.x = acc[i][0] + (HAS_BIAS ? bcol[0] : 0.f) + prev.x;
        v.y = acc[i][1] + (HAS_BIAS ? bcol[1] : 0.f) + prev.y;
        v.z = acc[i][2] + (HAS_BIAS ? bcol[2] : 0.f) + prev.z;
        v.w = acc[i][3] + (HAS_BIAS ? bcol[3] : 0.f) + prev.w;
        *(float4*)Crow = v;
    }
}

// -------- Layer-1 LSTM cell (fwd+bwd fused via index), writes comb ----------
__global__ void __launch_bounds__(256) cell1(int t) {
    int idx = blockIdx.x * 256 + threadIdx.x;     // < 2*256*512 = 262144
    int z = idx >> 17;                            // direction
    int r = idx & 131071;
    int b = r >> 9;
    int j = r & 511;
    const float* g = g_X1 + (size_t)z * ((size_t)TT * BB * H4)
                          + (size_t)t * (BB * H4) + (size_t)b * H4;
    float ig = sigf(g[j]);
    float fg = sigf(g[HH + j]);
    float gg = tanhf(g[2 * HH + j]);
    float og = sigf(g[3 * HH + j]);
    float cn = fg * g_c1[idx] + ig * gg;
    g_c1[idx] = cn;
    float hn = og * tanhf(cn);
    g_h1[idx] = hn;
    g_comb[(size_t)t * (BB * H2) + (size_t)b * H2 + (size_t)z * HH + j] = hn;
}

// -------- Layer-2 LSTM cell ------------------------------------------------
__global__ void __launch_bounds__(256) cell2(int t) {
    int idx = blockIdx.x * 256 + threadIdx.x;     // < 256*1024 = 262144
    int b = idx >> 10;
    int j = idx & 1023;
    const float* g = g_Gs + (size_t)t * (BB * H8) + (size_t)b * H8;
    float ig = sigf(g[j]);
    float fg = sigf(g[H2 + j]);
    float gg = tanhf(g[2 * H2 + j]);
    float og = sigf(g[3 * H2 + j]);
    float cn = fg * g_cs[idx] + ig * gg;
    g_cs[idx] = cn;
    g_hs[idx] = og * tanhf(cn);
}

// -------- Final classifier: out = sigmoid(hs @ Wl^T + bl), [256,2] ----------
__global__ void __launch_bounds__(256) final_logits(
    const float* __restrict__ Wl, const float* __restrict__ bl,
    float* __restrict__ out)
{
    int b = blockIdx.x;
    int tid = threadIdx.x;
    float s0 = 0.f, s1 = 0.f;
    const float* hrow = g_hs + (size_t)b * H2;
    for (int k = tid; k < H2; k += 256) {
        float hv = hrow[k];
        s0 += hv * Wl[k];
        s1 += hv * Wl[H2 + k];
    }
    __shared__ float r0[256], r1[256];
    r0[tid] = s0; r1[tid] = s1;
    __syncthreads();
    for (int s = 128; s > 0; s >>= 1) {
        if (tid < s) { r0[tid] += r0[tid + s]; r1[tid] += r1[tid + s]; }
        __syncthreads();
    }
    if (tid == 0) {
        out[b * 2 + 0] = 1.f / (1.f + expf(-(r0[0] + bl[0])));
        out[b * 2 + 1] = 1.f / (1.f + expf(-(r1[0] + bl[1])));
    }
}

extern "C" void kernel_launch(void* const* d_in, const int* in_sizes, int n_in,
                              void* d_out, int out_size)
{
    const float* x     = (const float*)d_in[0];
    const float* Wf_ih = (const float*)d_in[1];
    const float* Wf_hh = (const float*)d_in[2];
    const float* bf    = (const float*)d_in[3];
    const float* Wb_ih = (const float*)d_in[4];
    const float* Wb_hh = (const float*)d_in[5];
    const float* bb    = (const float*)d_in[6];
    const float* Ws_ih = (const float*)d_in[7];
    const float* Ws_hh = (const float*)d_in[8];
    const float* bs    = (const float*)d_in[9];
    const float* Wl    = (const float*)d_in[10];
    const float* bl    = (const float*)d_in[11];
    float* out = (float*)d_out;
    (void)in_sizes; (void)n_in; (void)out_size;

    float *X1, *comb, *Gs, *Whh1, *h1, *hs;
    cudaGetSymbolAddress((void**)&X1,   g_X1);
    cudaGetSymbolAddress((void**)&comb, g_comb);
    cudaGetSymbolAddress((void**)&Gs,   g_Gs);
    cudaGetSymbolAddress((void**)&Whh1, g_Whh1);
    cudaGetSymbolAddress((void**)&h1,   g_h1);
    cudaGetSymbolAddress((void**)&hs,   g_hs);

    // Reset recurrent state each replay
    zero_state<<<1024, 256>>>();

    // Pack layer-1 recurrent weights [2][4H][H]
    cudaMemcpyAsync(Whh1,            Wf_hh, sizeof(float) * H4 * HH,
                    cudaMemcpyDeviceToDevice);
    cudaMemcpyAsync(Whh1 + H4 * HH,  Wb_hh, sizeof(float) * H4 * HH,
                    cudaMemcpyDeviceToDevice);

    // Layer-1 input projections, all timesteps at once.
    // fwd: X1[0][t][b][:] = x[b,t,:] @ Wf_ih^T + bf
    gemm64<false, true><<<dim3(H4 / 64, BB / 64, TT), 256>>>(
        x, TT * DD, (long long)DD,
        Wf_ih, DD, 0,
        bf,
        X1, H4, (long long)BB * H4,
        DD);
    // bwd: X1[1][t][b][:] = x[b,T-1-t,:] @ Wb_ih^T + bb
    gemm64<false, true><<<dim3(H4 / 64, BB / 64, TT), 256>>>(
        x + (size_t)(TT - 1) * DD, TT * DD, -(long long)DD,
        Wb_ih, DD, 0,
        bb,
        X1 + (size_t)TT * BB * H4, H4, (long long)BB * H4,
        DD);

    // Layer-1 recurrence (fwd+bwd batched via z)
    for (int t = 0; t < TT; ++t) {
        gemm64<true, false><<<dim3(H4 / 64, BB / 64, 2), 256>>>(
            h1, HH, (long long)BB * HH,
            Whh1, HH, (long long)H4 * HH,
            nullptr,
            X1 + (size_t)t * BB * H4, H4, (long long)TT * BB * H4,
            HH);
        cell1<<<1024, 256>>>(t);
    }

    // Layer-2 input projection, all timesteps: Gs = comb @ Ws_ih^T + bs
    gemm64<false, true><<<dim3(H8 / 64, (TT * BB) / 64, 1), 256>>>(
        comb, H2, 0,
        Ws_ih, H2, 0,
        bs,
        Gs, H8, 0,
        H2);

    // Layer-2 recurrence
    for (int t = 0; t < TT; ++t) {
        gemm64<true, false><<<dim3(H8 / 64, BB / 64, 1), 256>>>(
            hs, H2, 0,
            Ws_hh, H2, 0,
            nullptr,
            Gs + (size_t)t * BB * H8, H8, 0,
            H2);
        cell2<<<1024, 256>>>(t);
    }

    final_logits<<<BB, 256>>>(Wl, bl, out);
}

// round 7
// speedup vs baseline: 1.7683x; 1.7683x over previous
#include <cuda_runtime.h>
#include <cuda_bf16.h>
#include <cstdint>

// Problem constants
#define BB 256      // batch
#define TT 128      // time
#define DD 256      // input dim
#define HH 512      // layer1 hidden
#define H2 1024     // 2H
#define H4 2048     // 4H
#define H8 4096     // 8H

// -------- Device scratch (no allocations allowed) --------
__device__ float g_X1[2u * TT * BB * H4];           // layer-1 gate preacts [2][T][B][4H]
__device__ float g_comb[(size_t)TT * BB * H2];      // [T][B][2H]
__device__ float g_Gs[(size_t)TT * BB * H8];        // layer-2 gate preacts [T][B][8H]
__device__ float g_Whh1[2u * H4 * HH];              // packed layer-1 recurrent weights
__device__ float g_h1[2 * BB * HH];
__device__ float g_c1[2 * BB * HH];
__device__ float g_hs[BB * H2];
__device__ float g_cs[BB * H2];

__device__ __forceinline__ float sigf(float x) { return 1.f / (1.f + expf(-x)); }

__device__ __forceinline__ uint32_t f2tf(float f) {
    uint32_t r;
    asm("cvt.rna.tf32.f32 %0, %1;" : "=r"(r) : "f"(f));
    return r;
}

__device__ __forceinline__ void mma_tf32(float* c, const uint32_t* a,
                                         uint32_t b0, uint32_t b1) {
    asm volatile(
        "mma.sync.aligned.m16n8k8.row.col.f32.tf32.tf32.f32 "
        "{%0,%1,%2,%3}, {%4,%5,%6,%7}, {%8,%9}, {%0,%1,%2,%3};\n"
        : "+f"(c[0]), "+f"(c[1]), "+f"(c[2]), "+f"(c[3])
        : "r"(a[0]), "r"(a[1]), "r"(a[2]), "r"(a[3]), "r"(b0), "r"(b1));
}

// -------- zero init of recurrent state (graph is replayed -> must reset) ----
__global__ void zero_state() {
    int i = blockIdx.x * blockDim.x + threadIdx.x;   // 262144 threads
    if (i < 2 * BB * HH) { g_h1[i] = 0.f; g_c1[i] = 0.f; }
    if (i < BB * H2)     { g_hs[i] = 0.f; g_cs[i] = 0.f; }
}

// ===========================================================================
// Projection GEMM (tf32 mma): C = A @ W^T + bias
// CTA tile 128(M) x 64(N), K chunk 32. 8 warps: 4(M) x 2(N), warp tile 32x32.
// blockIdx.z shifts A/C for time/direction batching.
// ===========================================================================
__global__ void __launch_bounds__(256) gemm_tf32(
    const float* __restrict__ A, long long lda, long long sAz,
    const float* __restrict__ W, long long ldw,
    const float* __restrict__ bias,
    float* __restrict__ C, long long ldc, long long sCz,
    int K)
{
    __shared__ uint32_t As[128][36];   // 18.4 KB
    __shared__ uint32_t Bs[64 * 36];   //  9.2 KB

    A += (long long)blockIdx.z * sAz;
    C += (long long)blockIdx.z * sCz;

    const int tid = threadIdx.x;
    const int w = tid >> 5, l = tid & 31;
    const int wm = w >> 1, wn = w & 1;
    const int grp = l >> 2, tig = l & 3;
    const long long m0 = (long long)blockIdx.y * 128;
    const long long n0 = (long long)blockIdx.x * 64;

    float acc[2][4][4];
#pragma unroll
    for (int i = 0; i < 2; ++i)
#pragma unroll
        for (int j = 0; j < 4; ++j)
#pragma unroll
            for (int k = 0; k < 4; ++k) acc[i][j][k] = 0.f;

    for (int k0 = 0; k0 < K; k0 += 32) {
        __syncthreads();
        // A: 128x32 -> 4 float4 per thread
#pragma unroll
        for (int i = 0; i < 4; ++i) {
            int idx = tid + i * 256;       // over 128 rows x 8 f4
            int r = idx >> 3, c4 = idx & 7;
            float4 v = *(const float4*)(A + (m0 + r) * lda + k0 + c4 * 4);
            uint32_t* dst = &As[r][c4 * 4];
            dst[0] = f2tf(v.x); dst[1] = f2tf(v.y);
            dst[2] = f2tf(v.z); dst[3] = f2tf(v.w);
        }
        // W: 64x32 -> 2 float4 per thread
#pragma unroll
        for (int i = 0; i < 2; ++i) {
            int idx = tid + i * 256;       // over 64 rows x 8 f4
            int r = idx >> 3, c4 = idx & 7;
            float4 v = *(const float4*)(W + (n0 + r) * ldw + k0 + c4 * 4);
            uint32_t* dst = &Bs[r * 36 + c4 * 4];
            dst[0] = f2tf(v.x); dst[1] = f2tf(v.y);
            dst[2] = f2tf(v.z); dst[3] = f2tf(v.w);
        }
        __syncthreads();
#pragma unroll
        for (int kk = 0; kk < 32; kk += 8) {
            uint32_t a[2][4];
#pragma unroll
            for (int mf = 0; mf < 2; ++mf) {
                int r = wm * 32 + mf * 16 + grp;
                a[mf][0] = As[r][kk + tig];
                a[mf][1] = As[r + 8][kk + tig];
                a[mf][2] = As[r][kk + 4 + tig];
                a[mf][3] = As[r + 8][kk + 4 + tig];
            }
#pragma unroll
            for (int nf = 0; nf < 4; ++nf) {
                int br = (wn * 32 + nf * 8 + grp) * 36;
                uint32_t b0 = Bs[br + kk + tig];
                uint32_t b1 = Bs[br + kk + 4 + tig];
                mma_tf32(acc[0][nf], a[0], b0, b1);
                mma_tf32(acc[1][nf], a[1], b0, b1);
            }
        }
    }

    // epilogue: bias + store
#pragma unroll
    for (int mf = 0; mf < 2; ++mf) {
#pragma unroll
        for (int nf = 0; nf < 4; ++nf) {
            long long row = m0 + wm * 32 + mf * 16 + grp;
            long long col = n0 + wn * 32 + nf * 8 + 2 * tig;
            float bv0 = bias ? bias[col] : 0.f;
            float bv1 = bias ? bias[col + 1] : 0.f;
            float2 v0 = make_float2(acc[mf][nf][0] + bv0, acc[mf][nf][1] + bv1);
            float2 v1 = make_float2(acc[mf][nf][2] + bv0, acc[mf][nf][3] + bv1);
            *(float2*)(C + row * ldc + col) = v0;
            *(float2*)(C + (row + 8) * ldc + col) = v1;
        }
    }
}

// ===========================================================================
// Fused LSTM step: gates = Gpre + h @ Whh^T, then cell update, state write.
// CTA: 32 batch rows x 64 hidden cols x all 4 gates.
// 8 warps: warp w -> gate (w>>1), col-half (w&1); warp tile 32x32.
// grid: (BB/32, HID/64, NDIR)
// ===========================================================================
template <int HID>
__global__ void __launch_bounds__(256) lstm_step(
    const float* __restrict__ h_in,   // [NDIR][BB][HID]
    const float* __restrict__ Whh,    // [NDIR][4*HID][HID]
    const float* __restrict__ Gpre,   // + z*zGs + b*4*HID + col
    long long zGs,
    float* __restrict__ c_st,         // [NDIR][BB][HID]
    float* __restrict__ h_out,        // [NDIR][BB][HID]
    float* __restrict__ comb,         // layer-1 only (else null)
    int t)
{
    __shared__ uint32_t As[32][36];        // 4.6 KB
    __shared__ uint32_t Bs[256 * 36];      // 36.9 KB (reused as epilogue stage)

    const int z = blockIdx.z;
    const int b0 = blockIdx.x * 32;
    const int j0 = blockIdx.y * 64;
    const float* Ab = h_in + (size_t)z * BB * HID;
    const float* Wb = Whh + (size_t)z * 4 * HID * HID;

    const int tid = threadIdx.x;
    const int w = tid >> 5, l = tid & 31;
    const int g = w >> 1, nh = w & 1;
    const int grp = l >> 2, tig = l & 3;

    float acc[2][4][4];
#pragma unroll
    for (int i = 0; i < 2; ++i)
#pragma unroll
        for (int j = 0; j < 4; ++j)
#pragma unroll
            for (int k = 0; k < 4; ++k) acc[i][j][k] = 0.f;

    for (int k0 = 0; k0 < HID; k0 += 32) {
        __syncthreads();
        // A: 32x32 -> 1 float4 per thread
        {
            int r = tid >> 3, c4 = tid & 7;
            float4 v = *(const float4*)(Ab + (size_t)(b0 + r) * HID + k0 + c4 * 4);
            uint32_t* dst = &As[r][c4 * 4];
            dst[0] = f2tf(v.x); dst[1] = f2tf(v.y);
            dst[2] = f2tf(v.z); dst[3] = f2tf(v.w);
        }
        // B: 256 rows (4 gates x 64 cols) x 32 -> 8 float4 per thread
#pragma unroll
        for (int i = 0; i < 8; ++i) {
            int idx = tid + i * 256;       // over 256 rows x 8 f4
            int r = idx >> 3, c4 = idx & 7;
            int gg = r >> 6, jj = r & 63;
            float4 v = *(const float4*)(Wb + (size_t)(gg * HID + j0 + jj) * HID + k0 + c4 * 4);
            uint32_t* dst = &Bs[r * 36 + c4 * 4];
            dst[0] = f2tf(v.x); dst[1] = f2tf(v.y);
            dst[2] = f2tf(v.z); dst[3] = f2tf(v.w);
        }
        __syncthreads();
#pragma unroll
        for (int kk = 0; kk < 32; kk += 8) {
            uint32_t a[2][4];
#pragma unroll
            for (int mf = 0; mf < 2; ++mf) {
                int r = mf * 16 + grp;
                a[mf][0] = As[r][kk + tig];
                a[mf][1] = As[r + 8][kk + tig];
                a[mf][2] = As[r][kk + 4 + tig];
                a[mf][3] = As[r + 8][kk + 4 + tig];
            }
#pragma unroll
            for (int nf = 0; nf < 4; ++nf) {
                int br = (g * 64 + nh * 32 + nf * 8 + grp) * 36;
                uint32_t b0 = Bs[br + kk + tig];
                uint32_t b1 = Bs[br + kk + 4 + tig];
                mma_tf32(acc[0][nf], a[0], b0, b1);
                mma_tf32(acc[1][nf], a[1], b0, b1);
            }
        }
    }

    // Stage accumulators: S[gcol * 33 + row], gcol in [0,256), row in [0,32)
    __syncthreads();
    float* S = (float*)Bs;
#pragma unroll
    for (int mf = 0; mf < 2; ++mf) {
#pragma unroll
        for (int nf = 0; nf < 4; ++nf) {
            int row = mf * 16 + grp;
            int gc = g * 64 + nh * 32 + nf * 8 + 2 * tig;
            S[gc * 33 + row] = acc[mf][nf][0];
            S[(gc + 1) * 33 + row] = acc[mf][nf][1];
            S[gc * 33 + row + 8] = acc[mf][nf][2];
            S[(gc + 1) * 33 + row + 8] = acc[mf][nf][3];
        }
    }
    __syncthreads();

    // Cell update: 32 rows x 64 cols -> 8 per thread
#pragma unroll
    for (int i = 0; i < 8; ++i) {
        int p = tid + i * 256;
        int jc = p & 63, r = p >> 6;
        int b = b0 + r;
        const float* gp = Gpre + (size_t)z * zGs + (size_t)b * 4 * HID + j0 + jc;
        float iv = S[jc * 33 + r] + gp[0];
        float fv = S[(64 + jc) * 33 + r] + gp[HID];
        float gv = S[(128 + jc) * 33 + r] + gp[2 * HID];
        float ov = S[(192 + jc) * 33 + r] + gp[3 * HID];
        size_t si = (size_t)z * BB * HID + (size_t)b * HID + j0 + jc;
        float cn = sigf(fv) * c_st[si] + sigf(iv) * tanhf(gv);
        c_st[si] = cn;
        float hn = sigf(ov) * tanhf(cn);
        h_out[si] = hn;
        if (comb)
            comb[(size_t)t * BB * H2 + (size_t)b * H2 + (size_t)z * HH + j0 + jc] = hn;
    }
}

// -------- Final classifier: out = sigmoid(hs @ Wl^T + bl), [256,2] ----------
__global__ void __launch_bounds__(256) final_logits(
    const float* __restrict__ Wl, const float* __restrict__ bl,
    float* __restrict__ out)
{
    int b = blockIdx.x;
    int tid = threadIdx.x;
    float s0 = 0.f, s1 = 0.f;
    const float* hrow = g_hs + (size_t)b * H2;
    for (int k = tid; k < H2; k += 256) {
        float hv = hrow[k];
        s0 += hv * Wl[k];
        s1 += hv * Wl[H2 + k];
    }
    __shared__ float r0[256], r1[256];
    r0[tid] = s0; r1[tid] = s1;
    __syncthreads();
    for (int s = 128; s > 0; s >>= 1) {
        if (tid < s) { r0[tid] += r0[tid + s]; r1[tid] += r1[tid + s]; }
        __syncthreads();
    }
    if (tid == 0) {
        out[b * 2 + 0] = 1.f / (1.f + expf(-(r0[0] + bl[0])));
        out[b * 2 + 1] = 1.f / (1.f + expf(-(r1[0] + bl[1])));
    }
}

extern "C" void kernel_launch(void* const* d_in, const int* in_sizes, int n_in,
                              void* d_out, int out_size)
{
    const float* x     = (const float*)d_in[0];
    const float* Wf_ih = (const float*)d_in[1];
    const float* Wf_hh = (const float*)d_in[2];
    const float* bf    = (const float*)d_in[3];
    const float* Wb_ih = (const float*)d_in[4];
    const float* Wb_hh = (const float*)d_in[5];
    const float* bb    = (const float*)d_in[6];
    const float* Ws_ih = (const float*)d_in[7];
    const float* Ws_hh = (const float*)d_in[8];
    const float* bs    = (const float*)d_in[9];
    const float* Wl    = (const float*)d_in[10];
    const float* bl    = (const float*)d_in[11];
    float* out = (float*)d_out;
    (void)in_sizes; (void)n_in; (void)out_size;

    float *X1, *comb, *Gs, *Whh1, *h1, *c1, *hs, *cs;
    cudaGetSymbolAddress((void**)&X1,   g_X1);
    cudaGetSymbolAddress((void**)&comb, g_comb);
    cudaGetSymbolAddress((void**)&Gs,   g_Gs);
    cudaGetSymbolAddress((void**)&Whh1, g_Whh1);
    cudaGetSymbolAddress((void**)&h1,   g_h1);
    cudaGetSymbolAddress((void**)&c1,   g_c1);
    cudaGetSymbolAddress((void**)&hs,   g_hs);
    cudaGetSymbolAddress((void**)&cs,   g_cs);

    // Reset recurrent state each replay
    zero_state<<<1024, 256>>>();

    // Pack layer-1 recurrent weights [2][4H][H]
    cudaMemcpyAsync(Whh1,           Wf_hh, sizeof(float) * H4 * HH,
                    cudaMemcpyDeviceToDevice);
    cudaMemcpyAsync(Whh1 + H4 * HH, Wb_hh, sizeof(float) * H4 * HH,
                    cudaMemcpyDeviceToDevice);

    // Layer-1 input projections (all timesteps at once, z = time)
    gemm_tf32<<<dim3(H4 / 64, BB / 128, TT), 256>>>(
        x, (long long)TT * DD, (long long)DD,
        Wf_ih, DD, bf,
        X1, H4, (long long)BB * H4, DD);
    gemm_tf32<<<dim3(H4 / 64, BB / 128, TT), 256>>>(
        x + (size_t)(TT - 1) * DD, (long long)TT * DD, -(long long)DD,
        Wb_ih, DD, bb,
        X1 + (size_t)TT * BB * H4, H4, (long long)BB * H4, DD);

    // Layer-1 recurrence (fwd + bwd batched via z), cell fused in-kernel
    for (int t = 0; t < TT; ++t) {
        lstm_step<HH><<<dim3(BB / 32, HH / 64, 2), 256>>>(
            h1, Whh1,
            X1 + (size_t)t * BB * H4, (long long)TT * BB * H4,
            c1, h1, comb, t);
    }

    // Layer-2 input projection: Gs = comb @ Ws_ih^T + bs
    gemm_tf32<<<dim3(H8 / 64, (TT * BB) / 128, 1), 256>>>(
        comb, H2, 0,
        Ws_ih, H2, bs,
        Gs, H8, 0, H2);

    // Layer-2 recurrence, cell fused
    for (int t = 0; t < TT; ++t) {
        lstm_step<H2><<<dim3(BB / 32, H2 / 64, 1), 256>>>(
            hs, Ws_hh,
            Gs + (size_t)t * BB * H8, 0,
            cs, hs, nullptr, t);
    }

    final_logits<<<BB, 256>>>(Wl, bl, out);
}